// round 6
// baseline (speedup 1.0000x reference)
#include <cuda_runtime.h>
#include <cuda_bf16.h>

// Dead-code-eliminated Net2 BSDE recurrence.
// ARITHMETIC IS BIT-FROZEN to the passing trajectory (rel_err 1.627573e-05):
// the recurrence is chaotic near u=50 (per-step Lyapunov factor ~1.3), so any
// rounding change is a correctness lottery. All FP expressions are verbatim
// from the passing Round-5 kernel (incl. the bit-exact two-FMA div3).
//
// Round-6 change (bit-neutral, selection topology only): the drift select is
// re-nested so the deep `mid` chain feeds the OUTER select directly:
//     inner = (u<50) ? low : high          (both shallow, ready early)
//     f     = (u<50 || u>=70) ? inner : mid
// This is value-identical in all three regions but removes one 4-cyc FSEL from
// the 40-iteration dependent chain. u0's load is also hoisted to the top so it
// issues with the first global-load batch.

#define D_DIM   100
#define N_STEPS 40
#define NWARPS  32
#define NTHREADS (NWARPS * 32)   // 1024

__device__ __forceinline__ float div3(float x) {
    // Correctly-rounded x/3 (== FDIV bits): Brisebarre-Muller two-FMA scheme.
    const float C_HI = 0.33333334f;       // RN(1/3)
    const float C_LO = -9.9341075e-09f;   // RN(1/3 - C_HI) = -1/(3*2^25)
    return __fmaf_rn(x, C_HI, x * C_LO);
}

__global__ void net2_u_kernel(const float* __restrict__ x0,
                              const float* __restrict__ tlist,
                              const float* __restrict__ noise,   // (N_STEPS, D, 1)
                              const float* __restrict__ u0,
                              const float* __restrict__ gu0,     // (D, 1)
                              float* __restrict__ out) {
    __shared__ float term3[N_STEPS];
    __shared__ float s_dt[N_STEPS];

    const int tid  = threadIdx.x;
    const int warp = tid >> 5;
    const int lane = tid & 31;

    // Issue the serial-phase operand loads with the very first load batch.
    float u = 0.0f;
    if (tid == 0) u = u0[0];
    if (tid < N_STEPS) s_dt[tid] = tlist[tid];

    // Frozen per-step dot: lane-stride-32 accumulate + 5-level shuffle tree
    // + s * sqrtf(tlist[k]). Warps 0-7 run two steps INTERLEAVED (same bits,
    // better ILP); warps 8-31 run one.
    if (warp < 8) {
        const int k0 = warp, k1 = warp + 32;
        float s0 = 0.0f, s1 = 0.0f;
        const float* n0 = noise + k0 * D_DIM;
        const float* n1 = noise + k1 * D_DIM;
        #pragma unroll
        for (int i = lane; i < D_DIM; i += 32) {
            float gu_i = 0.2f * x0[i] * gu0[i];
            s0 += gu_i * n0[i];
            s1 += gu_i * n1[i];
        }
        #pragma unroll
        for (int off = 16; off > 0; off >>= 1) {
            s0 += __shfl_down_sync(0xFFFFFFFFu, s0, off);
            s1 += __shfl_down_sync(0xFFFFFFFFu, s1, off);
        }
        if (lane == 0) {
            term3[k0] = s0 * sqrtf(tlist[k0]);
            term3[k1] = s1 * sqrtf(tlist[k1]);
        }
    } else {
        const int k = warp;
        float s = 0.0f;
        const float* nk = noise + k * D_DIM;
        #pragma unroll
        for (int i = lane; i < D_DIM; i += 32) {
            float gu_i = 0.2f * x0[i] * gu0[i];
            s += gu_i * nk[i];
        }
        #pragma unroll
        for (int off = 16; off > 0; off >>= 1)
            s += __shfl_down_sync(0xFFFFFFFFu, s, off);
        if (lane == 0)
            term3[k] = s * sqrtf(tlist[k]);
    }

    __syncthreads();

    if (tid == 0) {
        #pragma unroll
        for (int k = 0; k < N_STEPS; k++) {
            float dt = s_dt[k];
            // Verbatim frozen branch expressions.
            float low  = div3(-0.02f * u) - 0.02f * u;
            float high = div3(-0.002f * u) - 0.02f * u;
            float mid  = div3(-(70.0f - 50.0f) / (0.02f - 0.2f) * (u - 50.0f)) * u
                         - (0.2f / 3.0f) * u - 0.02f * u;
            // Bit-neutral re-nested select: mid (deepest chain) in the outer
            // position; low/high resolved early.
            bool  lt50  = (u < 50.0f);
            float inner = lt50 ? low : high;
            float f     = (lt50 || (u >= 70.0f)) ? inner : mid;
            u = u - f * dt + term3[k];   // frozen update shape
        }
        out[0] = u;
    }
}

extern "C" void kernel_launch(void* const* d_in, const int* in_sizes, int n_in,
                              void* d_out, int out_size) {
    const float* x0    = (const float*)d_in[0];
    const float* tlist = (const float*)d_in[1];
    const float* noise = (const float*)d_in[2];
    const float* u0    = (const float*)d_in[3];
    const float* gu0   = (const float*)d_in[4];
    float* out = (float*)d_out;

    net2_u_kernel<<<1, NTHREADS>>>(x0, tlist, noise, u0, gu0, out);
}